// round 5
// baseline (speedup 1.0000x reference)
#include <cuda_runtime.h>
#include <math.h>
#include <stdint.h>

// ---------------------------------------------------------------------------
// BiLSTM: B=32, T=512, D=512, H=512.
//   K0: transpose x[b][t][d] -> g_xT[t][d][b]
//   K1: xg precompute, 512 thr, k-split 2, cp.async double-buffered x tiles
//   K2: persistent recurrence, 128 blocks x 512 threads, f32x2, k-split 2,
//       flag-array barrier per direction
// ---------------------------------------------------------------------------

#define BB 32
#define TT 512
#define DD 512
#define HH 512
#define G4 2048
#define NBLK 128

typedef unsigned long long ull;

__device__ float g_xT[(size_t)TT * DD * BB];      // [t][d][b]
__device__ float g_xg[(size_t)2 * TT * G4 * BB];  // [dir][t][g][b]
// h pair layout: float idx = (j>>2)*128 + lane*4 + (j&3)  (== ull[k4][lane][2])
__device__ float g_hp[2 * 2 * 16384];             // [buf][dir][...]
__device__ int   g_flags[NBLK];

__device__ __forceinline__ float sigmoidf_(float x) {
    return 1.0f / (1.0f + expf(-x));
}
__device__ __forceinline__ ull ffma2(ull a, ull b, ull c) {
    ull d;
    asm("fma.rn.f32x2 %0, %1, %2, %3;" : "=l"(d) : "l"(a), "l"(b), "l"(c));
    return d;
}
__device__ __forceinline__ ull add2(ull a, ull b) {
    ull d;
    asm("add.rn.f32x2 %0, %1, %2;" : "=l"(d) : "l"(a), "l"(b));
    return d;
}
__device__ __forceinline__ float sum2(ull v) {
    float a, b;
    asm("mov.b64 {%0, %1}, %2;" : "=f"(a), "=f"(b) : "l"(v));
    return a + b;
}
__device__ __forceinline__ void cpa16(uint32_t s, const void* g) {
    asm volatile("cp.async.cg.shared.global [%0], [%1], 16;" :: "r"(s), "l"(g));
}
__device__ __forceinline__ void cpa_commit() {
    asm volatile("cp.async.commit_group;");
}
template <int N> __device__ __forceinline__ void cpa_wait() {
    asm volatile("cp.async.wait_group %0;" :: "n"(N));
}

// ---------------------------------------------------------------------------
__global__ void init_kernel() {
    int i = blockIdx.x * blockDim.x + threadIdx.x;
    if (i < NBLK) g_flags[i] = 0;
    if (i < 2 * 2 * 16384) g_hp[i] = 0.f;
}

// ---------------------------------------------------------------------------
// K0: transpose (unchanged, passing)
// ---------------------------------------------------------------------------
__global__ void transpose_x(const float* __restrict__ x) {
    int t = blockIdx.x;
    int d0 = blockIdx.y * 32;
    __shared__ float tile[32][33];
    int tid = threadIdx.x;
    {
        int b = tid >> 3;
        int dq = (tid & 7) * 4;
        float4 v = *(const float4*)(x + ((size_t)(b * TT + t)) * DD + d0 + dq);
        tile[b][dq + 0] = v.x; tile[b][dq + 1] = v.y;
        tile[b][dq + 2] = v.z; tile[b][dq + 3] = v.w;
    }
    __syncthreads();
    {
        int d = tid >> 3;
        int bq = (tid & 7) * 4;
        float4 o;
        o.x = tile[bq + 0][d]; o.y = tile[bq + 1][d];
        o.z = tile[bq + 2][d]; o.w = tile[bq + 3][d];
        *(float4*)(g_xT + ((size_t)(t * DD + d0 + d)) * 32 + bq) = o;
    }
}

// ---------------------------------------------------------------------------
// half-k 4-row dot (W broadcast, v per-lane). k range [k0, k0+256)
// ---------------------------------------------------------------------------
__device__ __forceinline__ void dot4h(const float* __restrict__ sW,
                                      const float* __restrict__ sV,
                                      int wl, int lane, int k0, float a[4]) {
    const float* w0 = sW + (size_t)(wl     ) * 512 + k0;
    const float* w1 = sW + (size_t)(wl +  8) * 512 + k0;
    const float* w2 = sW + (size_t)(wl + 16) * 512 + k0;
    const float* w3 = sW + (size_t)(wl + 24) * 512 + k0;
    const float* v  = sV + (size_t)k0 * 32;
    float a0 = 0.f, a1 = 0.f, a2 = 0.f, a3 = 0.f;
#pragma unroll 4
    for (int k = 0; k < 256; k += 4) {
        float4 v0 = *(const float4*)(w0 + k);
        float4 v1 = *(const float4*)(w1 + k);
        float4 v2 = *(const float4*)(w2 + k);
        float4 v3 = *(const float4*)(w3 + k);
        float h0 = v[(k + 0) * 32 + lane];
        float h1 = v[(k + 1) * 32 + lane];
        float h2 = v[(k + 2) * 32 + lane];
        float h3 = v[(k + 3) * 32 + lane];
        a0 = fmaf(v0.x, h0, a0); a0 = fmaf(v0.y, h1, a0);
        a0 = fmaf(v0.z, h2, a0); a0 = fmaf(v0.w, h3, a0);
        a1 = fmaf(v1.x, h0, a1); a1 = fmaf(v1.y, h1, a1);
        a1 = fmaf(v1.z, h2, a1); a1 = fmaf(v1.w, h3, a1);
        a2 = fmaf(v2.x, h0, a2); a2 = fmaf(v2.y, h1, a2);
        a2 = fmaf(v2.z, h2, a2); a2 = fmaf(v2.w, h3, a2);
        a3 = fmaf(v3.x, h0, a3); a3 = fmaf(v3.y, h1, a3);
        a3 = fmaf(v3.z, h2, a3); a3 = fmaf(v3.w, h3, a3);
    }
    a[0] = a0; a[1] = a1; a[2] = a2; a[3] = a3;
}

// ---------------------------------------------------------------------------
// K1: xg precompute. grid (64 tchunks, 128 tiles). 512 threads, k-split 2.
// smem: sW 64KB + sX[2] 128KB = 192KB dynamic, + 4KB static reduction
// ---------------------------------------------------------------------------
__global__ void __launch_bounds__(512, 1)
xg_kernel(const float* __restrict__ Wihf, const float* __restrict__ Wihb,
          const float* __restrict__ bihf, const float* __restrict__ bhhf,
          const float* __restrict__ bihb, const float* __restrict__ bhhb) {
    extern __shared__ float smem[];
    float* sW = smem;                         // 32 x 512
    float* sX0 = smem + 16384;                // 512 x 32
    float* sX1 = smem + 32768;
    __shared__ float sRed[256][4];

    int tc = blockIdx.x;
    int ry = blockIdx.y;
    int dir = ry >> 6;
    int gbase = (ry & 63) * 32;
    const float* Wih = dir ? Wihb : Wihf;
    const float* bih = dir ? bihb : bihf;
    const float* bhh = dir ? bhhb : bhhf;
    int tid = threadIdx.x, w = tid >> 5, lane = tid & 31;
    int g2 = w >> 3, wl = w & 7;

    {   // W tile
        const float4* src = (const float4*)(Wih + (size_t)gbase * DD);
        float4* dst = (float4*)sW;
        for (int i = tid; i < 32 * 128; i += 512) dst[i] = src[i];
    }
    float bias[4];
#pragma unroll
    for (int q = 0; q < 4; q++) {
        int g = gbase + q * 8 + wl;
        bias[q] = bih[g] + bhh[g];
    }

    uint32_t sx0a = (uint32_t)__cvta_generic_to_shared(sX0);
    uint32_t sx1a = (uint32_t)__cvta_generic_to_shared(sX1);

    int t0 = tc * 8;
    {   // prologue: x tile for it=0
        const char* src = (const char*)(g_xT + (size_t)t0 * DD * 32);
#pragma unroll
        for (int i = 0; i < 8; i++)
            cpa16(sx0a + (tid + i * 512) * 16, src + (size_t)(tid + i * 512) * 16);
        cpa_commit();
    }
#pragma unroll 1
    for (int it = 0; it < 8; it++) {
        if (it < 7) {
            uint32_t dsta = ((it + 1) & 1) ? sx1a : sx0a;
            const char* src = (const char*)(g_xT + (size_t)(t0 + it + 1) * DD * 32);
#pragma unroll
            for (int i = 0; i < 8; i++)
                cpa16(dsta + (tid + i * 512) * 16, src + (size_t)(tid + i * 512) * 16);
            cpa_commit();
            cpa_wait<1>();
        } else {
            cpa_wait<0>();
        }
        __syncthreads();

        const float* sX = (it & 1) ? sX1 : sX0;
        float a[4];
        dot4h(sW, sX, wl, lane, g2 * 256, a);

        // reduce halves: upper warps deposit, lower warps add + store
        if (g2 == 1) {
            int rt_ = tid - 256;
            sRed[rt_][0] = a[0]; sRed[rt_][1] = a[1];
            sRed[rt_][2] = a[2]; sRed[rt_][3] = a[3];
        }
        __syncthreads();
        if (g2 == 0) {
            int t = t0 + it;
            float* outp = g_xg + (((size_t)dir * TT + t) * G4 + gbase) * 32;
#pragma unroll
            for (int q = 0; q < 4; q++) {
                int r = q * 8 + wl;
                __stcs(outp + (size_t)r * 32 + lane, a[q] + sRed[tid][q] + bias[q]);
            }
        }
        __syncthreads();
    }
}

// ---------------------------------------------------------------------------
// K2: persistent recurrence. 128 blocks x 512 threads (16 warps, k-split 2).
// Block = (dir, 8 units = 32 rows). Warp w: rows {wl,8+wl,16+wl,24+wl},
// k half = (w>>3). lane = batch. f32x2 dot, smem reduction, flag barrier.
// smem: sW 64KB + sH 64KB dynamic + ~8KB static
// ---------------------------------------------------------------------------
__global__ void __launch_bounds__(512, 1)
rec_kernel(const float* __restrict__ Whhf, const float* __restrict__ Whhb,
           const int* __restrict__ lengths, float* __restrict__ out) {
    extern __shared__ float smem[];
    float* sW = smem;                        // 32 rows x 512
    ull*   sHu = (ull*)(smem + 16384);       // [k4][lane][2] pairs
    __shared__ ull  sRed[256][4];            // 8KB
    __shared__ float sOut[32][8];

    int blk = blockIdx.x;
    int dir = blk >> 6;
    int jbase = (blk & 63) * 8;
    int tid = threadIdx.x, w = tid >> 5, lane = tid & 31;
    int g2 = w >> 3, wl = w & 7;
    const float* Whh = dir ? Whhb : Whhf;

    // W_hh slice once: local row r=g*8+u -> global row g*512+jbase+u
    for (int i = tid; i < 32 * 128; i += 512) {
        int r = i >> 7, c4 = i & 127;
        int g = r >> 3, u = r & 7;
        ((float4*)sW)[i] = ((const float4*)Whh)[(size_t)(g * HH + jbase + u) * 128 + c4];
    }

    int mylen = lengths[lane];
    int j = jbase + wl;
    float c = 0.f, h = 0.f;
    const float* xgd = g_xg + (size_t)dir * TT * G4 * 32;
    const int hoff = (j >> 2) * 128 + lane * 4 + (j & 3);
    // weight row pointers for this warp's k half
    const int k4base = g2 * 64;               // k4 index base (k = 4*k4)
    const float* wr0 = sW + (size_t)(wl     ) * 512 + 4 * k4base;
    const float* wr1 = sW + (size_t)(wl +  8) * 512 + 4 * k4base;
    const float* wr2 = sW + (size_t)(wl + 16) * 512 + 4 * k4base;
    const float* wr3 = sW + (size_t)(wl + 24) * 512 + 4 * k4base;

    for (int s = 0; s < TT; s++) {
        int t = dir ? (TT - 1 - s) : s;
        int buf = s & 1;

        // xg prefetch (only lower half needs it for pointwise)
        float xv0, xv1, xv2, xv3;
        if (g2 == 0) {
            const float* xgt = xgd + (size_t)t * G4 * 32;
            xv0 = __ldcs(xgt + (size_t)(0 * HH + j) * 32 + lane);
            xv1 = __ldcs(xgt + (size_t)(1 * HH + j) * 32 + lane);
            xv2 = __ldcs(xgt + (size_t)(2 * HH + j) * 32 + lane);
            xv3 = __ldcs(xgt + (size_t)(3 * HH + j) * 32 + lane);
        }

        // stage h: 64KB, 512 threads x 8 x 16B, single pass
        {
            const ulonglong2* hsrc =
                (const ulonglong2*)(g_hp + (size_t)(buf * 2 + dir) * 16384);
            ulonglong2 r0 = __ldcg(hsrc + tid + 0 * 512);
            ulonglong2 r1 = __ldcg(hsrc + tid + 1 * 512);
            ulonglong2 r2 = __ldcg(hsrc + tid + 2 * 512);
            ulonglong2 r3 = __ldcg(hsrc + tid + 3 * 512);
            ulonglong2 r4 = __ldcg(hsrc + tid + 4 * 512);
            ulonglong2 r5 = __ldcg(hsrc + tid + 5 * 512);
            ulonglong2 r6 = __ldcg(hsrc + tid + 6 * 512);
            ulonglong2 r7 = __ldcg(hsrc + tid + 7 * 512);
            ulonglong2* sdst = (ulonglong2*)sHu;
            sdst[tid + 0 * 512] = r0; sdst[tid + 1 * 512] = r1;
            sdst[tid + 2 * 512] = r2; sdst[tid + 3 * 512] = r3;
            sdst[tid + 4 * 512] = r4; sdst[tid + 5 * 512] = r5;
            sdst[tid + 6 * 512] = r6; sdst[tid + 7 * 512] = r7;
        }
        __syncthreads();

        // half-k dot: 64 iters of 5 LDS.128 + 8 ffma2
        ull acc0 = 0, acc1 = 0, acc2 = 0, acc3 = 0;
        {
            const ulonglong2* hp_ = (const ulonglong2*)sHu + (size_t)k4base * 32 + lane;
#pragma unroll 4
            for (int i = 0; i < 64; i++) {
                ulonglong2 hp = hp_[i * 32];
                ulonglong2 wa = *(const ulonglong2*)(wr0 + 4 * i);
                ulonglong2 wb = *(const ulonglong2*)(wr1 + 4 * i);
                ulonglong2 wc = *(const ulonglong2*)(wr2 + 4 * i);
                ulonglong2 wd = *(const ulonglong2*)(wr3 + 4 * i);
                acc0 = ffma2(wa.x, hp.x, acc0); acc0 = ffma2(wa.y, hp.y, acc0);
                acc1 = ffma2(wb.x, hp.x, acc1); acc1 = ffma2(wb.y, hp.y, acc1);
                acc2 = ffma2(wc.x, hp.x, acc2); acc2 = ffma2(wc.y, hp.y, acc2);
                acc3 = ffma2(wd.x, hp.x, acc3); acc3 = ffma2(wd.y, hp.y, acc3);
            }
        }

        // combine k halves
        if (g2 == 1) {
            int rt_ = tid - 256;
            sRed[rt_][0] = acc0; sRed[rt_][1] = acc1;
            sRed[rt_][2] = acc2; sRed[rt_][3] = acc3;
        }
        __syncthreads();

        if (g2 == 0) {
            acc0 = add2(acc0, sRed[tid][0]);
            acc1 = add2(acc1, sRed[tid][1]);
            acc2 = add2(acc2, sRed[tid][2]);
            acc3 = add2(acc3, sRed[tid][3]);
            float gi = sigmoidf_(sum2(acc0) + xv0);
            float gf = sigmoidf_(sum2(acc1) + xv1);
            float gg = tanhf   (sum2(acc2) + xv2);
            float go = sigmoidf_(sum2(acc3) + xv3);
            float cn = gf * c + gi * gg;
            float hn = go * tanhf(cn);
            if (t < mylen) { c = cn; h = hn; }
            __stcg(g_hp + (size_t)((buf ^ 1) * 2 + dir) * 16384 + hoff, h);
            sOut[lane][wl] = h;
        }

        __threadfence();
        __syncthreads();
        if (tid == 0) ((volatile int*)g_flags)[blk] = s + 1;
        if (tid >= 64 && tid < 128) {
            int idx = tid - 64;
            int b = idx >> 1, half = idx & 1;
            float4 v;
            v.x = sOut[b][half * 4 + 0]; v.y = sOut[b][half * 4 + 1];
            v.z = sOut[b][half * 4 + 2]; v.w = sOut[b][half * 4 + 3];
            *(float4*)(out + ((size_t)(b * TT + t)) * 1024 + dir * HH + jbase + half * 4) = v;
        }
        if (tid < 64) {
            volatile int* f = (volatile int*)&g_flags[dir * 64 + tid];
            while (*f < s + 1) { }
        }
        __syncthreads();
    }
}

// ---------------------------------------------------------------------------
extern "C" void kernel_launch(void* const* d_in, const int* in_sizes, int n_in,
                              void* d_out, int out_size) {
    const float* x      = (const float*)d_in[0];
    const int*   lens   = (const int*)  d_in[1];
    const float* W_ih_f = (const float*)d_in[2];
    const float* W_hh_f = (const float*)d_in[3];
    const float* b_ih_f = (const float*)d_in[4];
    const float* b_hh_f = (const float*)d_in[5];
    const float* W_ih_b = (const float*)d_in[6];
    const float* W_hh_b = (const float*)d_in[7];
    const float* b_ih_b = (const float*)d_in[8];
    const float* b_hh_b = (const float*)d_in[9];
    float* out = (float*)d_out;

    cudaFuncSetAttribute(xg_kernel,  cudaFuncAttributeMaxDynamicSharedMemorySize, 196608);
    cudaFuncSetAttribute(rec_kernel, cudaFuncAttributeMaxDynamicSharedMemorySize, 131072);

    init_kernel<<<256, 256>>>();
    transpose_x<<<dim3(TT, DD / 32), 256>>>(x);
    xg_kernel<<<dim3(64, 128), 512, 196608>>>(W_ih_f, W_ih_b, b_ih_f, b_hh_f, b_ih_b, b_hh_b);
    rec_kernel<<<NBLK, 512, 131072>>>(W_hh_f, W_hh_b, lens, out);
}